// round 4
// baseline (speedup 1.0000x reference)
#include <cuda_runtime.h>
#include <math.h>

// ---------------- problem constants ----------------
#define BATCH 4
#define NPIX  65536      // 256*256
#define LHW   64         // latent grid 64x64
#define CLAT  32

// per-batch modulated weight scratch layout (floats)
#define OFF0 0           // 36*128
#define OFF1 4608        // 129*128
#define OFF2 21120
#define OFF3 37632
#define OFF4 54144       // 129*2
#define WSTRIDE 54404    // padded to a multiple of 4 floats (16B) for float4 access

__device__ float g_wmod[BATCH * WSTRIDE];

// ---------------- kernel A: modulate + column-normalize weights ----------------
// one warp per (batch, layer, output column). 514 columns per batch.
__global__ void modulate_kernel(
    const float* __restrict__ w0, const float* __restrict__ w1,
    const float* __restrict__ w2, const float* __restrict__ w3,
    const float* __restrict__ w4,
    const float* __restrict__ m0, const float* __restrict__ m1,
    const float* __restrict__ m2, const float* __restrict__ m3,
    const float* __restrict__ m4)
{
    int gw   = (blockIdx.x * blockDim.x + threadIdx.x) >> 5;
    int lane = threadIdx.x & 31;
    if (gw >= BATCH * 514) return;
    int b = gw / 514;
    int r = gw % 514;
    int layer, o;
    if (r < 512) { layer = r >> 7; o = r & 127; }
    else         { layer = 4;      o = r - 512; }

    const float* w; const float* m; int fr, fo, off;
    switch (layer) {
      case 0:  w = w0; m = m0; fr = 35;  fo = 128; off = OFF0; break;
      case 1:  w = w1; m = m1; fr = 128; fo = 128; off = OFF1; break;
      case 2:  w = w2; m = m2; fr = 128; fo = 128; off = OFF2; break;
      case 3:  w = w3; m = m3; fr = 128; fo = 128; off = OFF3; break;
      default: w = w4; m = m4; fr = 128; fo = 2;   off = OFF4; break;
    }
    float* dst = g_wmod + (size_t)b * WSTRIDE + off;

    float ss = 0.f;
    for (int i = lane; i < fr; i += 32) {
        float v = w[i * fo + o] * m[((size_t)b * fr + i) * fo + o];
        ss += v * v;
    }
    #pragma unroll
    for (int s = 16; s; s >>= 1) ss += __shfl_xor_sync(0xffffffffu, ss, s);
    float inv = 1.f / fmaxf(sqrtf(ss), 1e-12f);
    for (int i = lane; i < fr; i += 32) {
        float v = w[i * fo + o] * m[((size_t)b * fr + i) * fo + o];
        dst[i * fo + o] = v * inv;
    }
    if (lane == 0) dst[fr * fo + o] = w[fr * fo + o];   // bias row, unmodulated
}

// ---------------- kernel B: per-pixel modulated MLP ----------------
// block = 128 pixels of one batch, 256 threads.
// SMEM: Ws[129][128] (weights, row-major), Hs[128][128] (hidden, TRANSPOSED: [feature][pixel])
// thread tile: 4 pixels x 16 outputs (pg = tid&31 -> pixel group, og = tid>>5 -> output group)
#define PIX 128
#define THREADS 256
#define WS_ELEMS (129 * 128)
#define SMEM_BYTES ((WS_ELEMS + 128 * PIX) * 4)

__global__ __launch_bounds__(THREADS, 1)
void hyponet_kernel(const float* __restrict__ coord,
                    const float* __restrict__ lat,
                    float* __restrict__ out)
{
    extern __shared__ float sm[];
    float* Ws = sm;                 // 16512 floats
    float* Hs = sm + WS_ELEMS;      // 16384 floats

    const int tid   = threadIdx.x;
    const int b     = blockIdx.x >> 9;          // 512 blocks per batch
    const int pbase = (blockIdx.x & 511) << 7;  // *128

    // ---- stage layer-0 inputs: rows 0..31 = bilinear latent, 32..34 = coord ----
    if (tid < PIX) {
        int p = tid;
        int n = pbase + p;
        int y = n >> 8, x = n & 255;
        const float* c = coord + ((size_t)b * NPIX + n) * 3;
        Hs[32 * PIX + p] = c[0];
        Hs[33 * PIX + p] = c[1];
        Hs[34 * PIX + p] = c[2];
        // half-pixel bilinear, 64 -> 256 (scale 4), edge-clamped
        float sy = (y + 0.5f) * 0.25f - 0.5f;
        float sx = (x + 0.5f) * 0.25f - 0.5f;
        float fy0 = floorf(sy), fx0 = floorf(sx);
        float fy = sy - fy0,    fx = sx - fx0;
        int y0 = max(0, min(LHW - 1, (int)fy0));
        int y1 = max(0, min(LHW - 1, (int)fy0 + 1));
        int x0 = max(0, min(LHW - 1, (int)fx0));
        int x1 = max(0, min(LHW - 1, (int)fx0 + 1));
        float w00 = (1.f - fy) * (1.f - fx);
        float w01 = (1.f - fy) * fx;
        float w10 = fy * (1.f - fx);
        float w11 = fy * fx;
        const float* base = lat + (size_t)b * LHW * LHW * CLAT;
        const float4* q00 = (const float4*)(base + ((y0 * LHW + x0) * CLAT));
        const float4* q01 = (const float4*)(base + ((y0 * LHW + x1) * CLAT));
        const float4* q10 = (const float4*)(base + ((y1 * LHW + x0) * CLAT));
        const float4* q11 = (const float4*)(base + ((y1 * LHW + x1) * CLAT));
        #pragma unroll
        for (int k = 0; k < 8; k++) {
            float4 a = q00[k], bb = q01[k], cc = q10[k], dd = q11[k];
            Hs[(4 * k + 0) * PIX + p] = w00 * a.x + w01 * bb.x + w10 * cc.x + w11 * dd.x;
            Hs[(4 * k + 1) * PIX + p] = w00 * a.y + w01 * bb.y + w10 * cc.y + w11 * dd.y;
            Hs[(4 * k + 2) * PIX + p] = w00 * a.z + w01 * bb.z + w10 * cc.z + w11 * dd.z;
            Hs[(4 * k + 3) * PIX + p] = w00 * a.w + w01 * bb.w + w10 * cc.w + w11 * dd.w;
        }
    }

    const int offs[4] = {OFF0, OFF1, OFF2, OFF3};
    const int pg = tid & 31;   // pixel group (4 pixels)
    const int og = tid >> 5;   // output group (16 outputs)
    int fr = 35;               // real fan-in of layer 0

    for (int l = 0; l < 4; l++) {
        // load modulated weights for this layer (vectorized; counts divisible by 4)
        {
            const float4* src = (const float4*)(g_wmod + (size_t)b * WSTRIDE + offs[l]);
            int cnt = ((fr + 1) * 128) >> 2;
            float4* dst = (float4*)Ws;
            for (int idx = tid; idx < cnt; idx += THREADS) dst[idx] = src[idx];
        }
        __syncthreads();

        float acc[4][16];
        #pragma unroll
        for (int oo = 0; oo < 16; oo++) {
            float bsv = Ws[fr * 128 + og * 16 + oo];   // bias row
            acc[0][oo] = bsv; acc[1][oo] = bsv; acc[2][oo] = bsv; acc[3][oo] = bsv;
        }

        #pragma unroll 4
        for (int i = 0; i < fr; i++) {
            float4 h = *(const float4*)&Hs[i * PIX + pg * 4];
            #pragma unroll
            for (int q = 0; q < 4; q++) {
                float4 wv = *(const float4*)&Ws[i * 128 + og * 16 + q * 4];
                acc[0][q * 4 + 0] += h.x * wv.x;
                acc[1][q * 4 + 0] += h.y * wv.x;
                acc[2][q * 4 + 0] += h.z * wv.x;
                acc[3][q * 4 + 0] += h.w * wv.x;
                acc[0][q * 4 + 1] += h.x * wv.y;
                acc[1][q * 4 + 1] += h.y * wv.y;
                acc[2][q * 4 + 1] += h.z * wv.y;
                acc[3][q * 4 + 1] += h.w * wv.y;
                acc[0][q * 4 + 2] += h.x * wv.z;
                acc[1][q * 4 + 2] += h.y * wv.z;
                acc[2][q * 4 + 2] += h.z * wv.z;
                acc[3][q * 4 + 2] += h.w * wv.z;
                acc[0][q * 4 + 3] += h.x * wv.w;
                acc[1][q * 4 + 3] += h.y * wv.w;
                acc[2][q * 4 + 3] += h.z * wv.w;
                acc[3][q * 4 + 3] += h.w * wv.w;
            }
        }
        __syncthreads();   // all reads of Hs/Ws done before overwrite

        #pragma unroll
        for (int oo = 0; oo < 16; oo++) {
            float4 v;
            v.x = __sinf(acc[0][oo]);
            v.y = __sinf(acc[1][oo]);
            v.z = __sinf(acc[2][oo]);
            v.w = __sinf(acc[3][oo]);
            *(float4*)&Hs[(og * 16 + oo) * PIX + pg * 4] = v;
        }
        __syncthreads();
        fr = 128;
    }

    // ---- layer 4: 128 -> 2, + output bias 0.5 ----
    {
        const float* src = g_wmod + (size_t)b * WSTRIDE + OFF4;
        for (int idx = tid; idx < 258; idx += THREADS) Ws[idx] = src[idx];
        __syncthreads();
        int p = tid >> 1, o = tid & 1;
        float acc = Ws[128 * 2 + o];   // bias
        #pragma unroll 8
        for (int i = 0; i < 128; i++)
            acc += Hs[i * PIX + p] * Ws[i * 2 + o];
        out[((size_t)b * NPIX + pbase + p) * 2 + o] = acc + 0.5f;
    }
}

// ---------------- launch ----------------
extern "C" void kernel_launch(void* const* d_in, const int* in_sizes, int n_in,
                              void* d_out, int out_size)
{
    const float* coord = (const float*)d_in[0];
    const float* lat   = (const float*)d_in[1];

    // modulate: 4 batches * 514 columns = 2056 warps
    int mod_threads = 2056 * 32;
    modulate_kernel<<<(mod_threads + 255) / 256, 256>>>(
        (const float*)d_in[2], (const float*)d_in[3], (const float*)d_in[4],
        (const float*)d_in[5], (const float*)d_in[6],
        (const float*)d_in[7], (const float*)d_in[8], (const float*)d_in[9],
        (const float*)d_in[10], (const float*)d_in[11]);

    cudaFuncSetAttribute(hyponet_kernel,
                         cudaFuncAttributeMaxDynamicSharedMemorySize, SMEM_BYTES);
    hyponet_kernel<<<BATCH * (NPIX / PIX), THREADS, SMEM_BYTES>>>(
        coord, lat, (float*)d_out);
}

// round 6
// speedup vs baseline: 3.2467x; 3.2467x over previous
#include <cuda_runtime.h>
#include <math.h>
#include <stdint.h>

// ---------------- problem constants ----------------
#define BATCH 4
#define NPIX  65536      // 256*256
#define LHW   64
#define CLAT  32

// per-batch scratch (floats). Weight tiles stored transposed [n][kpad],
// XOR-swizzled: element (n,k) at n*kpad + (k ^ (4*(n&7))).
#define OFFB0    0       // 128 x 64   (8192 floats, K 40 padded to 64, zero-filled)
#define OFFB1    8192    // 128 x 128  (16384)
#define OFFB2    24576
#define OFFB3    40960
#define OFF_BIAS 57344   // 4 * 128 bias rows (fp32)
#define OFF_W4   57856   // 129*2 normalized W4 + bias row (fp32)
#define WSTRIDE  58368   // 16B-multiple

__device__ __align__(16) float g_wmod[BATCH * WSTRIDE];

// ================= PTX helpers (sm_100-baseline safe) =================
#define MBARRIER_INIT(mb, cnt) \
    asm volatile("mbarrier.init.shared.b64 [%0], %1;" :: "r"((uint32_t)(mb)), "r"((uint32_t)(cnt)) : "memory")
#define MBARRIER_EXPECT_TX(mb, bytes) \
    asm volatile("mbarrier.arrive.expect_tx.shared.b64 _, [%0], %1;" \
                 :: "r"((uint32_t)(mb)), "r"((uint32_t)(bytes)) : "memory")
#define MBARRIER_WAIT_PARITY(mb, par) do { \
    uint32_t _mb = (uint32_t)(mb), _p = (uint32_t)(par), _done; \
    asm volatile("{\n\t.reg .pred p;\n\t" \
        "mbarrier.try_wait.parity.acquire.cta.shared::cta.b64 p, [%1], %2;\n\t" \
        "selp.b32 %0, 1, 0, p;\n\t}" : "=r"(_done) : "r"(_mb), "r"(_p) : "memory"); \
    if (!_done) { \
        asm volatile("{\n\t.reg .pred P1;\n\t" \
            "WL_%=:\n\t" \
            "mbarrier.try_wait.parity.acquire.cta.shared::cta.b64 P1, [%0], %1, 0x989680;\n\t" \
            "@P1 bra.uni WD_%=;\n\t" \
            "bra.uni WL_%=;\n\t" \
            "WD_%=:\n\t}" :: "r"(_mb), "r"(_p) : "memory"); \
    } \
} while (0)
#define BULK_G2S(dst, src, bytes, mb) \
    asm volatile("cp.async.bulk.shared::cluster.global.mbarrier::complete_tx::bytes [%0], [%1], %2, [%3];" \
                 :: "r"((uint32_t)(dst)), "l"(src), "r"((uint32_t)(bytes)), "r"((uint32_t)(mb)) : "memory")

__device__ __forceinline__ uint32_t smem_to_u32(const void* p) {
    uint32_t a;
    asm("{ .reg .u64 t; cvta.to.shared.u64 t, %1; cvt.u32.u64 %0, t; }" : "=r"(a) : "l"(p));
    return a;
}
__device__ __forceinline__ uint32_t f2tf32(float x) {
    uint32_t u;
    asm("cvt.rna.tf32.f32 %0, %1;" : "=r"(u) : "f"(x));
    return u;
}

// ---------------- kernel A: modulate + normalize + transpose/swizzle-pack ----------------
__global__ void modulate_kernel(
    const float* __restrict__ w0, const float* __restrict__ w1,
    const float* __restrict__ w2, const float* __restrict__ w3,
    const float* __restrict__ w4,
    const float* __restrict__ m0, const float* __restrict__ m1,
    const float* __restrict__ m2, const float* __restrict__ m3,
    const float* __restrict__ m4)
{
    int gw   = (blockIdx.x * blockDim.x + threadIdx.x) >> 5;
    int lane = threadIdx.x & 31;
    if (gw >= BATCH * 514) return;
    int b = gw / 514;
    int r = gw % 514;
    int layer, o;
    if (r < 512) { layer = r >> 7; o = r & 127; }
    else         { layer = 4;      o = r - 512; }

    float* g = g_wmod + (size_t)b * WSTRIDE;

    if (layer < 4) {
        const float* w; const float* m; int fr, off, kpad;
        switch (layer) {
          case 0:  w = w0; m = m0; fr = 35;  off = OFFB0; kpad = 64;  break;
          case 1:  w = w1; m = m1; fr = 128; off = OFFB1; kpad = 128; break;
          case 2:  w = w2; m = m2; fr = 128; off = OFFB2; kpad = 128; break;
          default: w = w3; m = m3; fr = 128; off = OFFB3; kpad = 128; break;
        }
        float ss = 0.f;
        for (int k = lane; k < fr; k += 32) {
            float v = w[k * 128 + o] * m[((size_t)b * fr + k) * 128 + o];
            ss += v * v;
        }
        #pragma unroll
        for (int s = 16; s; s >>= 1) ss += __shfl_xor_sync(0xffffffffu, ss, s);
        float inv = 1.f / fmaxf(sqrtf(ss), 1e-12f);
        int sw = 4 * (o & 7);
        for (int k = lane; k < kpad; k += 32) {
            float v = 0.f;
            if (k < fr) v = w[k * 128 + o] * m[((size_t)b * fr + k) * 128 + o] * inv;
            g[off + o * kpad + (k ^ sw)] = __uint_as_float(f2tf32(v));
        }
        if (lane == 0) g[OFF_BIAS + layer * 128 + o] = w[fr * 128 + o];
    } else {
        float ss = 0.f;
        for (int k = lane; k < 128; k += 32) {
            float v = w4[k * 2 + o] * m4[((size_t)b * 128 + k) * 2 + o];
            ss += v * v;
        }
        #pragma unroll
        for (int s = 16; s; s >>= 1) ss += __shfl_xor_sync(0xffffffffu, ss, s);
        float inv = 1.f / fmaxf(sqrtf(ss), 1e-12f);
        for (int k = lane; k < 128; k += 32)
            g[OFF_W4 + k * 2 + o] = w4[k * 2 + o] * m4[((size_t)b * 128 + k) * 2 + o] * inv;
        if (lane == 0) g[OFF_W4 + 256 + o] = w4[128 * 2 + o];
    }
}

// ---------------- kernel B: tf32 mma.sync MLP ----------------
// CTA = 128 pixels, 256 threads (8 warps: 4 M-groups x 2 N-groups, warp tile 32x64).
#define AP 132           // padded A row stride (floats)
#define MB_B     0
#define BIAS_F   16      // float idx (byte 64), 512 floats
#define W4_F     528     // 258 floats
#define A_B      4096    // byte offset of A tile, 128*132*4 = 67584
#define WBUF0_B  71680   // 65536
#define WBUF1_B  137216  // 65536
#define SMEM_BYTES 202752

// warp-tile MMA over one layer: A[128][AP] tf32 bits, W[n][KP] swizzled tf32 bits
template<int KSTEPS, int KP>
__device__ __forceinline__ void mma_compute(
    const uint32_t* __restrict__ Asm, const uint32_t* __restrict__ Wsm,
    int mbase, int nbase, int lr, int lc, float acc[2][8][4])
{
    const int s24 = (4 * lr) & 24;
    const int x0  = lc + ((4 * lr) & 4);
    const int x1  = x0 ^ 4;
    #pragma unroll
    for (int ks = 0; ks < KSTEPS; ks++) {
        const int kb  = ks * 8;
        const int kbs = kb ^ s24;
        uint32_t a[2][4];
        #pragma unroll
        for (int mt = 0; mt < 2; mt++) {
            int r0 = (mbase + mt * 16 + lr) * AP + kb + lc;
            a[mt][0] = Asm[r0];
            a[mt][1] = Asm[r0 + 8 * AP];
            a[mt][2] = Asm[r0 + 4];
            a[mt][3] = Asm[r0 + 8 * AP + 4];
        }
        #pragma unroll
        for (int q = 0; q < 8; q++) {
            int base = (nbase + q * 8 + lr) * KP + kbs;
            uint32_t b0 = Wsm[base + x0];
            uint32_t b1 = Wsm[base + x1];
            #pragma unroll
            for (int mt = 0; mt < 2; mt++) {
                asm volatile(
                    "mma.sync.aligned.m16n8k8.row.col.f32.tf32.tf32.f32 "
                    "{%0,%1,%2,%3}, {%4,%5,%6,%7}, {%8,%9}, {%0,%1,%2,%3};"
                    : "+f"(acc[mt][q][0]), "+f"(acc[mt][q][1]),
                      "+f"(acc[mt][q][2]), "+f"(acc[mt][q][3])
                    : "r"(a[mt][0]), "r"(a[mt][1]), "r"(a[mt][2]), "r"(a[mt][3]),
                      "r"(b0), "r"(b1));
            }
        }
    }
}

__global__ __launch_bounds__(256)
void hyponet_kernel(const float* __restrict__ coord,
                    const float* __restrict__ lat,
                    float* __restrict__ out)
{
    extern __shared__ __align__(1024) char smem[];
    float*    smf = (float*)smem;
    uint32_t* Au  = (uint32_t*)(smem + A_B);
    float*    Af  = (float*)(smem + A_B);
    const uint32_t sb = smem_to_u32(smem);
    const uint32_t mb = sb + MB_B;

    const int tid  = threadIdx.x;
    const int warp = tid >> 5, lane = tid & 31;
    const int lr = lane >> 2, lc = lane & 3;
    const int mbase = (warp & 3) * 32;
    const int nbase = (warp >> 2) * 64;
    const int b     = blockIdx.x >> 9;
    const int pbase = (blockIdx.x & 511) << 7;
    const float* gw = g_wmod + (size_t)b * WSTRIDE;

    if (tid == 0) MBARRIER_INIT(mb, 1);
    __syncthreads();
    if (tid == 0) {
        MBARRIER_EXPECT_TX(mb, 32768);
        BULK_G2S(sb + WBUF0_B, gw + OFFB0, 32768, mb);
    }

    // ---- prologue ----
    if (tid < 128) {
        int p = tid, n = pbase + p;
        int y = n >> 8, x = n & 255;
        const float* c = coord + ((size_t)b * NPIX + n) * 3;
        float sy = (y + 0.5f) * 0.25f - 0.5f;
        float sx = (x + 0.5f) * 0.25f - 0.5f;
        float fy0 = floorf(sy), fx0 = floorf(sx);
        float fy = sy - fy0,    fx = sx - fx0;
        int y0 = max(0, min(LHW - 1, (int)fy0));
        int y1 = max(0, min(LHW - 1, (int)fy0 + 1));
        int x0 = max(0, min(LHW - 1, (int)fx0));
        int x1 = max(0, min(LHW - 1, (int)fx0 + 1));
        float w00 = (1.f - fy) * (1.f - fx), w01 = (1.f - fy) * fx;
        float w10 = fy * (1.f - fx),         w11 = fy * fx;
        const float* base = lat + (size_t)b * LHW * LHW * CLAT;
        const float4* q00 = (const float4*)(base + (y0 * LHW + x0) * CLAT);
        const float4* q01 = (const float4*)(base + (y0 * LHW + x1) * CLAT);
        const float4* q10 = (const float4*)(base + (y1 * LHW + x0) * CLAT);
        const float4* q11 = (const float4*)(base + (y1 * LHW + x1) * CLAT);
        uint32_t* arow = Au + p * AP;
        #pragma unroll
        for (int k = 0; k < 8; k++) {
            float4 a = q00[k], bb = q01[k], cc = q10[k], dd = q11[k];
            arow[4 * k + 0] = f2tf32(w00 * a.x + w01 * bb.x + w10 * cc.x + w11 * dd.x);
            arow[4 * k + 1] = f2tf32(w00 * a.y + w01 * bb.y + w10 * cc.y + w11 * dd.y);
            arow[4 * k + 2] = f2tf32(w00 * a.z + w01 * bb.z + w10 * cc.z + w11 * dd.z);
            arow[4 * k + 3] = f2tf32(w00 * a.w + w01 * bb.w + w10 * cc.w + w11 * dd.w);
        }
        arow[32] = f2tf32(c[0]);
        arow[33] = f2tf32(c[1]);
        arow[34] = f2tf32(c[2]);
        arow[35] = 0; arow[36] = 0; arow[37] = 0; arow[38] = 0; arow[39] = 0;
    } else {
        for (int i = tid - 128; i < 770; i += 128) smf[BIAS_F + i] = gw[OFF_BIAS + i];
    }
    __syncthreads();

    const int offb_next[3] = {OFFB1, OFFB2, OFFB3};

    #define LAYER_PASS(L, KS, KPV, WOFF_B) do { \
        MBARRIER_WAIT_PARITY(mb, (L) & 1); \
        if (tid == 0 && (L) < 3) { \
            MBARRIER_EXPECT_TX(mb, 65536); \
            BULK_G2S(sb + (((L) & 1) ? WBUF0_B : WBUF1_B), gw + offb_next[L], 65536, mb); \
        } \
        float acc[2][8][4] = {}; \
        mma_compute<KS, KPV>(Au, (const uint32_t*)(smem + (WOFF_B)), mbase, nbase, lr, lc, acc); \
        __syncthreads(); \
        const float* biasL = smf + BIAS_F + (L) * 128; \
        _Pragma("unroll") \
        for (int mt = 0; mt < 2; mt++) { \
            _Pragma("unroll") \
            for (int q = 0; q < 8; q++) { \
                int col0 = nbase + q * 8 + 2 * lc; \
                float2 bv = *(const float2*)(biasL + col0); \
                int r0 = mbase + mt * 16 + lr; \
                uint2 v01, v23; \
                v01.x = f2tf32(__sinf(acc[mt][q][0] + bv.x)); \
                v01.y = f2tf32(__sinf(acc[mt][q][1] + bv.y)); \
                v23.x = f2tf32(__sinf(acc[mt][q][2] + bv.x)); \
                v23.y = f2tf32(__sinf(acc[mt][q][3] + bv.y)); \
                *(uint2*)&Au[r0 * AP + col0]       = v01; \
                *(uint2*)&Au[(r0 + 8) * AP + col0] = v23; \
            } \
        } \
        __syncthreads(); \
    } while (0)

    LAYER_PASS(0, 5, 64, WBUF0_B);
    LAYER_PASS(1, 16, 128, WBUF1_B);
    LAYER_PASS(2, 16, 128, WBUF0_B);
    LAYER_PASS(3, 16, 128, WBUF1_B);
    #undef LAYER_PASS

    // ---- final: 128 -> 2 dot + 0.5 (fp32) ----
    {
        const float* w4 = smf + W4_F;
        int o = tid >> 7, p = tid & 127;
        float acc = w4[256 + o];
        const float* arow = Af + p * AP;
        #pragma unroll 8
        for (int k = 0; k < 128; k += 4) {
            float4 a = *(const float4*)(arow + k);
            acc += a.x * w4[(k + 0) * 2 + o];
            acc += a.y * w4[(k + 1) * 2 + o];
            acc += a.z * w4[(k + 2) * 2 + o];
            acc += a.w * w4[(k + 3) * 2 + o];
        }
        out[((size_t)b * NPIX + pbase + p) * 2 + o] = acc + 0.5f;
    }
}

// ---------------- launch ----------------
extern "C" void kernel_launch(void* const* d_in, const int* in_sizes, int n_in,
                              void* d_out, int out_size)
{
    const float* coord = (const float*)d_in[0];
    const float* lat   = (const float*)d_in[1];

    modulate_kernel<<<(2056 * 32 + 255) / 256, 256>>>(
        (const float*)d_in[2], (const float*)d_in[3], (const float*)d_in[4],
        (const float*)d_in[5], (const float*)d_in[6],
        (const float*)d_in[7], (const float*)d_in[8], (const float*)d_in[9],
        (const float*)d_in[10], (const float*)d_in[11]);

    cudaFuncSetAttribute(hyponet_kernel,
                         cudaFuncAttributeMaxDynamicSharedMemorySize, SMEM_BYTES);
    hyponet_kernel<<<BATCH * (NPIX / 128), 256, SMEM_BYTES>>>(coord, lat, (float*)d_out);
}